// round 13
// baseline (speedup 1.0000x reference)
#include <cuda_runtime.h>
#include <math.h>
#include <stdint.h>

// ============================================================================
// Euclidean loss, bulk-async datapath experiment.
// Each block: contiguous 64KiB/operand region, 2-stage cp.async.bulk pipeline
// of 8KiB tiles into SMEM, reduce from SMEM. Same grid shape as best (R3).
// ============================================================================

#define B_ROWS 16
#define D_LEN  2097152               // floats per row
#define TPB    256
#define BPR    128                   // blocks per row
#define NBLK   (BPR * B_ROWS)        // 2048 blocks
#define TILE_BYTES 8192              // per operand per stage
#define TILE_F4    (TILE_BYTES / 16) // 512 float4
#define NTILES     8                 // per operand per block: 8*8KiB = 64KiB
// per-block traffic = 2 ops * 64KiB = 128KiB; 2048 blocks * 128KiB = 256MiB ✓

__device__ float        g_rowsum[B_ROWS];
__device__ unsigned int g_arrived;

__device__ __forceinline__ uint32_t smem_u32(const void* p) {
    uint32_t a;
    asm("{ .reg .u64 t; cvta.to.shared.u64 t, %1; cvt.u32.u64 %0, t; }"
        : "=r"(a) : "l"(p));
    return a;
}

#define MBAR_INIT(addr, cnt) \
    asm volatile("mbarrier.init.shared.b64 [%0], %1;" :: "r"(addr), "r"(cnt) : "memory")
#define MBAR_EXPECT_TX(addr, bytes) \
    asm volatile("mbarrier.arrive.expect_tx.shared.b64 _, [%0], %1;" \
                 :: "r"(addr), "r"(bytes) : "memory")
#define BULK_G2S(dst, src, bytes, mbar) \
    asm volatile("cp.async.bulk.shared::cta.global.mbarrier::complete_tx::bytes " \
                 "[%0], [%1], %2, [%3];" \
                 :: "r"(dst), "l"(src), "r"(bytes), "r"(mbar) : "memory")

__device__ __forceinline__ void mbar_wait(uint32_t mbar, uint32_t parity) {
    asm volatile(
        "{\n\t"
        ".reg .pred P;\n\t"
        "W%=:\n\t"
        "mbarrier.try_wait.parity.acquire.cta.shared::cta.b64 P, [%0], %1, 0x989680;\n\t"
        "@P bra D%=;\n\t"
        "bra W%=;\n\t"
        "D%=:\n\t"
        "}"
        :: "r"(mbar), "r"(parity) : "memory");
}

__global__ __launch_bounds__(TPB, 4) void euclid_loss_kernel(
    const float* __restrict__ outp, const float* __restrict__ labp,
    float* __restrict__ dst)
{
    __shared__ __align__(128) float4 buf[2][2][TILE_F4];  // [stage][operand] 32 KiB
    __shared__ __align__(8) unsigned long long mbar_store[2];
    __shared__ float sm[TPB / 32];
    __shared__ bool  last;

    const int row = blockIdx.y;
    // Contiguous 64KiB (=16384 floats) per operand per block
    const char* __restrict__ oreg =
        (const char*)(outp + (size_t)row * D_LEN + (size_t)blockIdx.x * (NTILES * TILE_BYTES / 4));
    const char* __restrict__ lreg =
        (const char*)(labp + (size_t)row * D_LEN + (size_t)blockIdx.x * (NTILES * TILE_BYTES / 4));

    const uint32_t mb0 = smem_u32(&mbar_store[0]);
    const uint32_t mb1 = smem_u32(&mbar_store[1]);

    if (threadIdx.x == 0) {
        MBAR_INIT(mb0, 1);
        MBAR_INIT(mb1, 1);
        // fence so the async proxy sees the initialized barriers
        asm volatile("fence.proxy.async.shared::cta;" ::: "memory");
    }
    __syncthreads();

    // Prologue: fill both stages
    if (threadIdx.x == 0) {
#pragma unroll
        for (int t = 0; t < 2; ++t) {
            const uint32_t mb = t ? mb1 : mb0;
            MBAR_EXPECT_TX(mb, 2 * TILE_BYTES);
            BULK_G2S(smem_u32(&buf[t][0][0]), oreg + (size_t)t * TILE_BYTES, TILE_BYTES, mb);
            BULK_G2S(smem_u32(&buf[t][1][0]), lreg + (size_t)t * TILE_BYTES, TILE_BYTES, mb);
        }
    }

    float s0 = 0.0f, s1 = 0.0f, s2 = 0.0f, s3 = 0.0f;

    for (int t = 0; t < NTILES; ++t) {
        const int s = t & 1;
        const uint32_t mb = s ? mb1 : mb0;
        mbar_wait(mb, (t >> 1) & 1);

        // Consume: each thread reads 2 float4 per operand from SMEM
        float4 a0 = buf[s][0][threadIdx.x];
        float4 a1 = buf[s][0][threadIdx.x + TPB];
        float4 b0 = buf[s][1][threadIdx.x];
        float4 b1 = buf[s][1][threadIdx.x + TPB];

        float dx, dy, dz, dw;
        dx = a0.x - b0.x; dy = a0.y - b0.y; dz = a0.z - b0.z; dw = a0.w - b0.w;
        s0 = fmaf(dx, dx, s0); s1 = fmaf(dy, dy, s1);
        s2 = fmaf(dz, dz, s2); s3 = fmaf(dw, dw, s3);
        dx = a1.x - b1.x; dy = a1.y - b1.y; dz = a1.z - b1.z; dw = a1.w - b1.w;
        s0 = fmaf(dx, dx, s0); s1 = fmaf(dy, dy, s1);
        s2 = fmaf(dz, dz, s2); s3 = fmaf(dw, dw, s3);

        __syncthreads();  // all reads of stage s done before refill

        if (threadIdx.x == 0 && t + 2 < NTILES) {
            MBAR_EXPECT_TX(mb, 2 * TILE_BYTES);
            BULK_G2S(smem_u32(&buf[s][0][0]),
                     oreg + (size_t)(t + 2) * TILE_BYTES, TILE_BYTES, mb);
            BULK_G2S(smem_u32(&buf[s][1][0]),
                     lreg + (size_t)(t + 2) * TILE_BYTES, TILE_BYTES, mb);
        }
    }

    float sv = (s0 + s1) + (s2 + s3);

    // warp reduce
#pragma unroll
    for (int off = 16; off > 0; off >>= 1)
        sv += __shfl_down_sync(0xffffffffu, sv, off);

    if ((threadIdx.x & 31) == 0) sm[threadIdx.x >> 5] = sv;
    __syncthreads();

    if (threadIdx.x < 32) {
        float v = (threadIdx.x < TPB / 32) ? sm[threadIdx.x] : 0.0f;
#pragma unroll
        for (int off = 16; off > 0; off >>= 1)
            v += __shfl_down_sync(0xffffffffu, v, off);
        if (threadIdx.x == 0) {
            atomicAdd(&g_rowsum[row], v);
            __threadfence();
            unsigned int prev = atomicAdd(&g_arrived, 1u);
            last = (prev == (unsigned int)(NBLK - 1));
        }
    }
    __syncthreads();

    if (last) {
        __threadfence();
        if (threadIdx.x < 32) {
            float v = (threadIdx.x < B_ROWS) ? sqrtf(g_rowsum[threadIdx.x]) : 0.0f;
#pragma unroll
            for (int off = 16; off > 0; off >>= 1)
                v += __shfl_down_sync(0xffffffffu, v, off);
            if (threadIdx.x == 0) dst[0] = v * (1.0f / (float)B_ROWS);
            if (threadIdx.x < B_ROWS) g_rowsum[threadIdx.x] = 0.0f;
            if (threadIdx.x == 0)     g_arrived = 0u;
        }
    }
}

extern "C" void kernel_launch(void* const* d_in, const int* in_sizes, int n_in,
                              void* d_out, int out_size)
{
    const float* outp = (const float*)d_in[0];
    const float* labp = (const float*)d_in[1];
    float* dst = (float*)d_out;

    dim3 grid(BPR, B_ROWS);
    euclid_loss_kernel<<<grid, TPB>>>(outp, labp, dst);
}

// round 16
// speedup vs baseline: 1.0537x; 1.0537x over previous
#include <cuda_runtime.h>
#include <math.h>

// ============================================================================
// Euclidean-distance loss: mean_b sqrt(sum_d (out[b,d]-lab[b,d])^2)
// B=16, D=2^21 fp32. Reads 256 MiB (algorithmic minimum) -> HBM/LTS-bound.
//
// FINAL KERNEL — converged config, best of 11 measured variants.
// Measured floor: ~43.5us = 256MiB @ ~6.4TB/s sustained (path-independent
// ceiling: LDG.128 = LDG.256 = cp.async.bulk) + ~1.5us fixed overhead.
//   - single fused kernel: arrival-counter "last block" finalize (sqrt+mean),
//     scratch self-reset for graph-replay determinism
//   - 2048 blocks x 256 thr, occ 4/SM (best measured shape; multi-wave
//     work distribution beats single-wave and work-stealing variants)
//   - 8 front-batched LDG.128 per unrolled iter (~8 loads in flight/thread)
//   - 4 independent fp32 accumulators (breaks FMA RAW chain)
//   - __ldcs streaming loads (zero-reuse stream; don't pollute L2)
// ============================================================================

#define B_ROWS 16
#define D_LEN  2097152              // floats per row
#define D4     (D_LEN / 4)          // 524288 float4 per row
#define TPB    256
#define BPR    128                  // blocks per row
#define NBLK   (BPR * B_ROWS)       // 2048 total blocks
#define ITERS  (D4 / (TPB * BPR))   // 16 float4 per thread
#define BATCH  4                    // float4 loads in flight per operand
#define OUTER  (ITERS / BATCH)      // 4

// Scratch (zero-initialized at module load; last block resets after use so
// every graph replay starts from the same state — deterministic).
__device__ float        g_rowsum[B_ROWS];
__device__ unsigned int g_arrived;

__global__ __launch_bounds__(TPB, 4) void euclid_loss_kernel(
    const float* __restrict__ outp, const float* __restrict__ labp,
    float* __restrict__ dst)
{
    const int row = blockIdx.y;
    const float4* __restrict__ o = (const float4*)(outp + (size_t)row * D_LEN);
    const float4* __restrict__ l = (const float4*)(labp + (size_t)row * D_LEN);

    const int base   = blockIdx.x * TPB + threadIdx.x;  // float4 index
    const int stride = BPR * TPB;                       // 32768 float4

    float s0 = 0.0f, s1 = 0.0f, s2 = 0.0f, s3 = 0.0f;

#pragma unroll
    for (int i = 0; i < OUTER; ++i) {
        // Issue all 8 LDG.128 back-to-back (front-batched -> high MLP)
        float4 a0, a1, a2, a3, b0, b1, b2, b3;
        const int j0 = base + (i * BATCH + 0) * stride;
        const int j1 = base + (i * BATCH + 1) * stride;
        const int j2 = base + (i * BATCH + 2) * stride;
        const int j3 = base + (i * BATCH + 3) * stride;
        a0 = __ldcs(&o[j0]); a1 = __ldcs(&o[j1]);
        a2 = __ldcs(&o[j2]); a3 = __ldcs(&o[j3]);
        b0 = __ldcs(&l[j0]); b1 = __ldcs(&l[j1]);
        b2 = __ldcs(&l[j2]); b3 = __ldcs(&l[j3]);

        float dx, dy, dz, dw;
        dx = a0.x - b0.x; dy = a0.y - b0.y; dz = a0.z - b0.z; dw = a0.w - b0.w;
        s0 = fmaf(dx, dx, s0); s1 = fmaf(dy, dy, s1);
        s2 = fmaf(dz, dz, s2); s3 = fmaf(dw, dw, s3);

        dx = a1.x - b1.x; dy = a1.y - b1.y; dz = a1.z - b1.z; dw = a1.w - b1.w;
        s0 = fmaf(dx, dx, s0); s1 = fmaf(dy, dy, s1);
        s2 = fmaf(dz, dz, s2); s3 = fmaf(dw, dw, s3);

        dx = a2.x - b2.x; dy = a2.y - b2.y; dz = a2.z - b2.z; dw = a2.w - b2.w;
        s0 = fmaf(dx, dx, s0); s1 = fmaf(dy, dy, s1);
        s2 = fmaf(dz, dz, s2); s3 = fmaf(dw, dw, s3);

        dx = a3.x - b3.x; dy = a3.y - b3.y; dz = a3.z - b3.z; dw = a3.w - b3.w;
        s0 = fmaf(dx, dx, s0); s1 = fmaf(dy, dy, s1);
        s2 = fmaf(dz, dz, s2); s3 = fmaf(dw, dw, s3);
    }

    float s = (s0 + s1) + (s2 + s3);

    // warp reduce
#pragma unroll
    for (int off = 16; off > 0; off >>= 1)
        s += __shfl_down_sync(0xffffffffu, s, off);

    __shared__ float sm[TPB / 32];
    __shared__ bool  last;
    if ((threadIdx.x & 31) == 0) sm[threadIdx.x >> 5] = s;
    __syncthreads();

    if (threadIdx.x < 32) {
        float v = (threadIdx.x < TPB / 32) ? sm[threadIdx.x] : 0.0f;
#pragma unroll
        for (int off = 16; off > 0; off >>= 1)
            v += __shfl_down_sync(0xffffffffu, v, off);
        if (threadIdx.x == 0) {
            atomicAdd(&g_rowsum[row], v);
            __threadfence();  // make row partial globally visible before arrival
            unsigned int prev = atomicAdd(&g_arrived, 1u);
            last = (prev == (unsigned int)(NBLK - 1));
        }
    }
    __syncthreads();

    // Final block: all partials are in g_rowsum (fence+atomic handshake).
    if (last) {
        __threadfence();  // acquire: see all other blocks' g_rowsum adds
        if (threadIdx.x < 32) {
            float v = (threadIdx.x < B_ROWS) ? sqrtf(g_rowsum[threadIdx.x]) : 0.0f;
#pragma unroll
            for (int off = 16; off > 0; off >>= 1)
                v += __shfl_down_sync(0xffffffffu, v, off);
            if (threadIdx.x == 0) dst[0] = v * (1.0f / (float)B_ROWS);
            // Reset scratch for the next graph replay.
            if (threadIdx.x < B_ROWS) g_rowsum[threadIdx.x] = 0.0f;
            if (threadIdx.x == 0)     g_arrived = 0u;
        }
    }
}

extern "C" void kernel_launch(void* const* d_in, const int* in_sizes, int n_in,
                              void* d_out, int out_size)
{
    const float* outp = (const float*)d_in[0];
    const float* labp = (const float*)d_in[1];
    float* dst = (float*)d_out;

    dim3 grid(BPR, B_ROWS);
    euclid_loss_kernel<<<grid, TPB>>>(outp, labp, dst);
}